// round 8
// baseline (speedup 1.0000x reference)
#include <cuda_runtime.h>
#include <cuda_bf16.h>

// ColorQuantizer: out = PALETTE[argmin_p ||MLP(x) - pal_p||]
// (stop_gradient(hard - soft) + soft == hard numerically; softmax/sqrt are
//  monotone so argmax(weights) == argmin(distance) == argmax(dot - 0.5*|pal|^2))
//
// Inputs (metadata order): x[32,3,512,512] f32, W1[3,32], b1[32], W2[32,3], b2[3]
// Output: [32,3,512,512] f32
//
// 8 pixels per thread (4 f32x2 pairs), no k-loop. Halves weight-LDS per
// pixel and gives 4 independent FFMA2 chains per j-iteration for ILP.

typedef unsigned long long u64;

#define B_DIM  32
#define HW     262144          // 512*512
#define TPB    256
#define VEC    2               // float4 slots per channel per thread (8 px)
#define GRIDX  (HW / 4 / (TPB * VEC))   // 65536 / 512 = 128

__device__ __forceinline__ u64 pk2(float lo, float hi) {
    u64 d; asm("mov.b64 %0, {%1, %2};" : "=l"(d) : "f"(lo), "f"(hi)); return d;
}
__device__ __forceinline__ void up2(float& lo, float& hi, u64 d) {
    asm("mov.b64 {%0, %1}, %2;" : "=f"(lo), "=f"(hi) : "l"(d));
}
__device__ __forceinline__ u64 ffma2(u64 a, u64 b, u64 c) {
    u64 d; asm("fma.rn.f32x2 %0, %1, %2, %3;" : "=l"(d) : "l"(a), "l"(b), "l"(c));
    return d;
}

__global__ __launch_bounds__(TPB, 2) void color_quant_kernel(
    const float* __restrict__ x,
    const float* __restrict__ W1,   // [3][32] row-major
    const float* __restrict__ b1,   // [32]
    const float* __restrict__ W2,   // [32][3] row-major
    const float* __restrict__ b2,   // [3]
    float* __restrict__ out)
{
    // Shared: weights pre-duplicated into both halves of f32x2 lanes.
    // sW1[j]  = {w0,w0, w1,w1, w2,w2, b1,b1}        (2x LDS.128)
    // sW2[j]  = {u0,u0, u1,u1, u2,u2, 0,0}
    // sPal[p] = {px,px, py,py, pz,pz, c,c},  c = -0.5*|pal_p|^2
    __shared__ __align__(16) float sW1[32 * 8];
    __shared__ __align__(16) float sW2[32 * 8];
    __shared__ __align__(16) float sPal[16 * 8];
    __shared__ float sGat[48];      // palette gather table [16][3]

    const int tid = threadIdx.x;

    if (tid < 32) {
        const int j = tid;
        float w0 = W1[j], w1 = W1[32 + j], w2 = W1[64 + j], bb = b1[j];
        float4* v = (float4*)(sW1 + j * 8);
        v[0] = make_float4(w0, w0, w1, w1);
        v[1] = make_float4(w2, w2, bb, bb);
        float u0 = W2[3 * j], u1 = W2[3 * j + 1], u2 = W2[3 * j + 2];
        float4* q = (float4*)(sW2 + j * 8);
        q[0] = make_float4(u0, u0, u1, u1);
        q[1] = make_float4(u2, u2, 0.f, 0.f);
    }
    if (tid < 16) {
        // pal = (c/255)*2 - 1, each op round-to-nearest fp32 (matches numpy)
        const float C[16][3] = {
            {0,0,0},{255,255,255},{255,0,0},{0,255,0},{0,0,255},{255,255,0},
            {255,0,255},{0,255,255},{128,128,128},{128,0,0},{0,128,0},{0,0,128},
            {128,128,0},{128,0,128},{0,128,128},{192,192,192}};
        float px = __fsub_rn(__fmul_rn(__fdiv_rn(C[tid][0], 255.0f), 2.0f), 1.0f);
        float py = __fsub_rn(__fmul_rn(__fdiv_rn(C[tid][1], 255.0f), 2.0f), 1.0f);
        float pz = __fsub_rn(__fmul_rn(__fdiv_rn(C[tid][2], 255.0f), 2.0f), 1.0f);
        float n  = __fmaf_rn(pz, pz, __fmaf_rn(py, py, __fmul_rn(px, px)));
        float cc = -0.5f * n;
        float4* t = (float4*)(sPal + tid * 8);
        t[0] = make_float4(px, px, py, py);
        t[1] = make_float4(pz, pz, cc, cc);
        sGat[tid * 3 + 0] = px;
        sGat[tid * 3 + 1] = py;
        sGat[tid * 3 + 2] = pz;
    }
    __syncthreads();

    const float bz0 = b2[0], bz1 = b2[1], bz2 = b2[2];
    const u64 Bp0 = pk2(bz0, bz0), Bp1 = pk2(bz1, bz1), Bp2 = pk2(bz2, bz2);

    const float* xb = x   + (size_t)blockIdx.y * (3 * HW);
    float*       ob = out + (size_t)blockIdx.y * (3 * HW);
    const int it0 = blockIdx.x * (TPB * VEC) + tid;
    const int r0 = it0 * 4;             // first float4 (floats)
    const int r1 = (it0 + TPB) * 4;     // second float4

    const ulonglong2* w1v = (const ulonglong2*)sW1;
    const ulonglong2* w2v = (const ulonglong2*)sW2;
    const ulonglong2* pv  = (const ulonglong2*)sPal;

    // Load 8 pixels: 2 coalesced float4 per channel (6x LDG.128, max MLP)
    float4 c0a = *(const float4*)(xb + r0);
    float4 c0b = *(const float4*)(xb + r1);
    float4 c1a = *(const float4*)(xb + HW + r0);
    float4 c1b = *(const float4*)(xb + HW + r1);
    float4 c2a = *(const float4*)(xb + 2 * HW + r0);
    float4 c2b = *(const float4*)(xb + 2 * HW + r1);

    u64 X0[4], X1[4], X2[4];
    X0[0] = pk2(c0a.x, c0a.y); X0[1] = pk2(c0a.z, c0a.w);
    X0[2] = pk2(c0b.x, c0b.y); X0[3] = pk2(c0b.z, c0b.w);
    X1[0] = pk2(c1a.x, c1a.y); X1[1] = pk2(c1a.z, c1a.w);
    X1[2] = pk2(c1b.x, c1b.y); X1[3] = pk2(c1b.z, c1b.w);
    X2[0] = pk2(c2a.x, c2a.y); X2[1] = pk2(c2a.z, c2a.w);
    X2[2] = pk2(c2b.x, c2b.y); X2[3] = pk2(c2b.z, c2b.w);

    u64 A0[4], A1[4], A2[4];
    #pragma unroll
    for (int q = 0; q < 4; q++) { A0[q] = Bp0; A1[q] = Bp1; A2[q] = Bp2; }

    // fused layer1 (relu) + layer2; 4 independent pair-chains per j for ILP
    #pragma unroll 4
    for (int j = 0; j < 32; j++) {
        ulonglong2 Wa = w1v[2 * j];       // {w0w0, w1w1}
        ulonglong2 Wb = w1v[2 * j + 1];   // {w2w2, bb}
        ulonglong2 Ua = w2v[2 * j];       // {u0u0, u1u1}
        ulonglong2 Ub = w2v[2 * j + 1];   // {u2u2, 0}
        u64 h[4];
        #pragma unroll
        for (int q = 0; q < 4; q++) {
            u64 t = ffma2(X0[q], Wa.x, Wb.y);
            t = ffma2(X1[q], Wa.y, t);
            t = ffma2(X2[q], Wb.x, t);
            h[q] = t;
        }
        #pragma unroll
        for (int q = 0; q < 4; q++) {
            float lo, hi;
            up2(lo, hi, h[q]);
            lo = fmaxf(lo, 0.f); hi = fmaxf(hi, 0.f);
            h[q] = pk2(lo, hi);
        }
        #pragma unroll
        for (int q = 0; q < 4; q++) {
            A0[q] = ffma2(h[q], Ua.x, A0[q]);
            A1[q] = ffma2(h[q], Ua.y, A1[q]);
            A2[q] = ffma2(h[q], Ub.x, A2[q]);
        }
    }

    // argmax_p of (proc . pal_p - 0.5*|pal_p|^2); strict > keeps first index
    float bs[8];
    int   id[8];
    {
        ulonglong2 Pa = pv[0], Pb = pv[1];
        #pragma unroll
        for (int q = 0; q < 4; q++) {
            u64 t = ffma2(A0[q], Pa.x, Pb.y);
            t = ffma2(A1[q], Pa.y, t);
            t = ffma2(A2[q], Pb.x, t);
            up2(bs[2 * q], bs[2 * q + 1], t);
            id[2 * q] = 0; id[2 * q + 1] = 0;
        }
    }
    #pragma unroll 5
    for (int p = 1; p < 16; p++) {
        ulonglong2 Pa = pv[2 * p], Pb = pv[2 * p + 1];
        #pragma unroll
        for (int q = 0; q < 4; q++) {
            u64 t = ffma2(A0[q], Pa.x, Pb.y);
            t = ffma2(A1[q], Pa.y, t);
            t = ffma2(A2[q], Pb.x, t);
            float t0, t1; up2(t0, t1, t);
            if (t0 > bs[2 * q])     { bs[2 * q] = t0;     id[2 * q] = p; }
            if (t1 > bs[2 * q + 1]) { bs[2 * q + 1] = t1; id[2 * q + 1] = p; }
        }
    }

    // gather hard-quantized colors, store 2 coalesced STG.128 per channel
    float4 o;
    o = make_float4(sGat[id[0] * 3 + 0], sGat[id[1] * 3 + 0],
                    sGat[id[2] * 3 + 0], sGat[id[3] * 3 + 0]);
    *(float4*)(ob + r0) = o;
    o = make_float4(sGat[id[4] * 3 + 0], sGat[id[5] * 3 + 0],
                    sGat[id[6] * 3 + 0], sGat[id[7] * 3 + 0]);
    *(float4*)(ob + r1) = o;

    o = make_float4(sGat[id[0] * 3 + 1], sGat[id[1] * 3 + 1],
                    sGat[id[2] * 3 + 1], sGat[id[3] * 3 + 1]);
    *(float4*)(ob + HW + r0) = o;
    o = make_float4(sGat[id[4] * 3 + 1], sGat[id[5] * 3 + 1],
                    sGat[id[6] * 3 + 1], sGat[id[7] * 3 + 1]);
    *(float4*)(ob + HW + r1) = o;

    o = make_float4(sGat[id[0] * 3 + 2], sGat[id[1] * 3 + 2],
                    sGat[id[2] * 3 + 2], sGat[id[3] * 3 + 2]);
    *(float4*)(ob + 2 * HW + r0) = o;
    o = make_float4(sGat[id[4] * 3 + 2], sGat[id[5] * 3 + 2],
                    sGat[id[6] * 3 + 2], sGat[id[7] * 3 + 2]);
    *(float4*)(ob + 2 * HW + r1) = o;
}

extern "C" void kernel_launch(void* const* d_in, const int* in_sizes, int n_in,
                              void* d_out, int out_size) {
    const float* x  = (const float*)d_in[0];
    const float* W1 = (const float*)d_in[1];
    const float* b1 = (const float*)d_in[2];
    const float* W2 = (const float*)d_in[3];
    const float* b2 = (const float*)d_in[4];
    float* out = (float*)d_out;

    dim3 grid(GRIDX, B_DIM);   // 128 x 32 = 4096 CTAs, 8 px/thread
    dim3 block(TPB);
    color_quant_kernel<<<grid, block>>>(x, W1, b1, W2, b2, out);
}

// round 10
// speedup vs baseline: 1.0525x; 1.0525x over previous
#include <cuda_runtime.h>
#include <cuda_bf16.h>

// ColorQuantizer: out = PALETTE[argmin_p ||MLP(x) - pal_p||]
// (stop_gradient(hard - soft) + soft == hard numerically; softmax/sqrt are
//  monotone so argmax(weights) == argmin(distance) == argmax(dot - 0.5*|pal|^2))
//
// Inputs (metadata order): x[32,3,512,512] f32, W1[3,32], b1[32], W2[32,3], b2[3]
// Output: [32,3,512,512] f32
//
// R9: identical arithmetic to R8 (8 px/thread, f32x2 FFMA2 throughout), but
// __launch_bounds__(256, 3): regs 86 -> 85, 3 CTAs/SM = 24 warps (6/SMSP)
// to cover FFMA2/LDS latency. Kernel was latency-bound, not throughput-bound.

typedef unsigned long long u64;

#define B_DIM  32
#define HW     262144          // 512*512
#define TPB    256
#define VEC    2               // float4 slots per channel per thread (8 px)
#define GRIDX  (HW / 4 / (TPB * VEC))   // 65536 / 512 = 128

__device__ __forceinline__ u64 pk2(float lo, float hi) {
    u64 d; asm("mov.b64 %0, {%1, %2};" : "=l"(d) : "f"(lo), "f"(hi)); return d;
}
__device__ __forceinline__ void up2(float& lo, float& hi, u64 d) {
    asm("mov.b64 {%0, %1}, %2;" : "=f"(lo), "=f"(hi) : "l"(d));
}
__device__ __forceinline__ u64 ffma2(u64 a, u64 b, u64 c) {
    u64 d; asm("fma.rn.f32x2 %0, %1, %2, %3;" : "=l"(d) : "l"(a), "l"(b), "l"(c));
    return d;
}

__global__ __launch_bounds__(TPB, 3) void color_quant_kernel(
    const float* __restrict__ x,
    const float* __restrict__ W1,   // [3][32] row-major
    const float* __restrict__ b1,   // [32]
    const float* __restrict__ W2,   // [32][3] row-major
    const float* __restrict__ b2,   // [3]
    float* __restrict__ out)
{
    // Shared: weights pre-duplicated into both halves of f32x2 lanes.
    // sW1[j]  = {w0,w0, w1,w1, w2,w2, b1,b1}        (2x LDS.128)
    // sW2[j]  = {u0,u0, u1,u1, u2,u2, 0,0}
    // sPal[p] = {px,px, py,py, pz,pz, c,c},  c = -0.5*|pal_p|^2
    __shared__ __align__(16) float sW1[32 * 8];
    __shared__ __align__(16) float sW2[32 * 8];
    __shared__ __align__(16) float sPal[16 * 8];
    __shared__ float sGat[48];      // palette gather table [16][3]

    const int tid = threadIdx.x;

    if (tid < 32) {
        const int j = tid;
        float w0 = W1[j], w1 = W1[32 + j], w2 = W1[64 + j], bb = b1[j];
        float4* v = (float4*)(sW1 + j * 8);
        v[0] = make_float4(w0, w0, w1, w1);
        v[1] = make_float4(w2, w2, bb, bb);
        float u0 = W2[3 * j], u1 = W2[3 * j + 1], u2 = W2[3 * j + 2];
        float4* q = (float4*)(sW2 + j * 8);
        q[0] = make_float4(u0, u0, u1, u1);
        q[1] = make_float4(u2, u2, 0.f, 0.f);
    }
    if (tid < 16) {
        // pal = (c/255)*2 - 1, each op round-to-nearest fp32 (matches numpy)
        const float C[16][3] = {
            {0,0,0},{255,255,255},{255,0,0},{0,255,0},{0,0,255},{255,255,0},
            {255,0,255},{0,255,255},{128,128,128},{128,0,0},{0,128,0},{0,0,128},
            {128,128,0},{128,0,128},{0,128,128},{192,192,192}};
        float px = __fsub_rn(__fmul_rn(__fdiv_rn(C[tid][0], 255.0f), 2.0f), 1.0f);
        float py = __fsub_rn(__fmul_rn(__fdiv_rn(C[tid][1], 255.0f), 2.0f), 1.0f);
        float pz = __fsub_rn(__fmul_rn(__fdiv_rn(C[tid][2], 255.0f), 2.0f), 1.0f);
        float n  = __fmaf_rn(pz, pz, __fmaf_rn(py, py, __fmul_rn(px, px)));
        float cc = -0.5f * n;
        float4* t = (float4*)(sPal + tid * 8);
        t[0] = make_float4(px, px, py, py);
        t[1] = make_float4(pz, pz, cc, cc);
        sGat[tid * 3 + 0] = px;
        sGat[tid * 3 + 1] = py;
        sGat[tid * 3 + 2] = pz;
    }
    __syncthreads();

    const float bz0 = b2[0], bz1 = b2[1], bz2 = b2[2];
    const u64 Bp0 = pk2(bz0, bz0), Bp1 = pk2(bz1, bz1), Bp2 = pk2(bz2, bz2);

    const float* xb = x   + (size_t)blockIdx.y * (3 * HW);
    float*       ob = out + (size_t)blockIdx.y * (3 * HW);
    const int it0 = blockIdx.x * (TPB * VEC) + tid;
    const int r0 = it0 * 4;             // first float4 (floats)
    const int r1 = (it0 + TPB) * 4;     // second float4

    const ulonglong2* w1v = (const ulonglong2*)sW1;
    const ulonglong2* w2v = (const ulonglong2*)sW2;
    const ulonglong2* pv  = (const ulonglong2*)sPal;

    // Load 8 pixels: 2 coalesced float4 per channel (6x LDG.128, max MLP)
    float4 c0a = *(const float4*)(xb + r0);
    float4 c0b = *(const float4*)(xb + r1);
    float4 c1a = *(const float4*)(xb + HW + r0);
    float4 c1b = *(const float4*)(xb + HW + r1);
    float4 c2a = *(const float4*)(xb + 2 * HW + r0);
    float4 c2b = *(const float4*)(xb + 2 * HW + r1);

    u64 X0[4], X1[4], X2[4];
    X0[0] = pk2(c0a.x, c0a.y); X0[1] = pk2(c0a.z, c0a.w);
    X0[2] = pk2(c0b.x, c0b.y); X0[3] = pk2(c0b.z, c0b.w);
    X1[0] = pk2(c1a.x, c1a.y); X1[1] = pk2(c1a.z, c1a.w);
    X1[2] = pk2(c1b.x, c1b.y); X1[3] = pk2(c1b.z, c1b.w);
    X2[0] = pk2(c2a.x, c2a.y); X2[1] = pk2(c2a.z, c2a.w);
    X2[2] = pk2(c2b.x, c2b.y); X2[3] = pk2(c2b.z, c2b.w);

    u64 A0[4], A1[4], A2[4];
    #pragma unroll
    for (int q = 0; q < 4; q++) { A0[q] = Bp0; A1[q] = Bp1; A2[q] = Bp2; }

    // fused layer1 (relu) + layer2; 4 independent pair-chains per j for ILP
    #pragma unroll 4
    for (int j = 0; j < 32; j++) {
        ulonglong2 Wa = w1v[2 * j];       // {w0w0, w1w1}
        ulonglong2 Wb = w1v[2 * j + 1];   // {w2w2, bb}
        ulonglong2 Ua = w2v[2 * j];       // {u0u0, u1u1}
        ulonglong2 Ub = w2v[2 * j + 1];   // {u2u2, 0}
        u64 h[4];
        #pragma unroll
        for (int q = 0; q < 4; q++) {
            u64 t = ffma2(X0[q], Wa.x, Wb.y);
            t = ffma2(X1[q], Wa.y, t);
            t = ffma2(X2[q], Wb.x, t);
            h[q] = t;
        }
        #pragma unroll
        for (int q = 0; q < 4; q++) {
            float lo, hi;
            up2(lo, hi, h[q]);
            lo = fmaxf(lo, 0.f); hi = fmaxf(hi, 0.f);
            h[q] = pk2(lo, hi);
        }
        #pragma unroll
        for (int q = 0; q < 4; q++) {
            A0[q] = ffma2(h[q], Ua.x, A0[q]);
            A1[q] = ffma2(h[q], Ua.y, A1[q]);
            A2[q] = ffma2(h[q], Ub.x, A2[q]);
        }
    }

    // argmax_p of (proc . pal_p - 0.5*|pal_p|^2); strict > keeps first index
    float bs[8];
    int   id[8];
    {
        ulonglong2 Pa = pv[0], Pb = pv[1];
        #pragma unroll
        for (int q = 0; q < 4; q++) {
            u64 t = ffma2(A0[q], Pa.x, Pb.y);
            t = ffma2(A1[q], Pa.y, t);
            t = ffma2(A2[q], Pb.x, t);
            up2(bs[2 * q], bs[2 * q + 1], t);
            id[2 * q] = 0; id[2 * q + 1] = 0;
        }
    }
    #pragma unroll 5
    for (int p = 1; p < 16; p++) {
        ulonglong2 Pa = pv[2 * p], Pb = pv[2 * p + 1];
        #pragma unroll
        for (int q = 0; q < 4; q++) {
            u64 t = ffma2(A0[q], Pa.x, Pb.y);
            t = ffma2(A1[q], Pa.y, t);
            t = ffma2(A2[q], Pb.x, t);
            float t0, t1; up2(t0, t1, t);
            if (t0 > bs[2 * q])     { bs[2 * q] = t0;     id[2 * q] = p; }
            if (t1 > bs[2 * q + 1]) { bs[2 * q + 1] = t1; id[2 * q + 1] = p; }
        }
    }

    // gather hard-quantized colors, store 2 coalesced STG.128 per channel
    float4 o;
    o = make_float4(sGat[id[0] * 3 + 0], sGat[id[1] * 3 + 0],
                    sGat[id[2] * 3 + 0], sGat[id[3] * 3 + 0]);
    *(float4*)(ob + r0) = o;
    o = make_float4(sGat[id[4] * 3 + 0], sGat[id[5] * 3 + 0],
                    sGat[id[6] * 3 + 0], sGat[id[7] * 3 + 0]);
    *(float4*)(ob + r1) = o;

    o = make_float4(sGat[id[0] * 3 + 1], sGat[id[1] * 3 + 1],
                    sGat[id[2] * 3 + 1], sGat[id[3] * 3 + 1]);
    *(float4*)(ob + HW + r0) = o;
    o = make_float4(sGat[id[4] * 3 + 1], sGat[id[5] * 3 + 1],
                    sGat[id[6] * 3 + 1], sGat[id[7] * 3 + 1]);
    *(float4*)(ob + HW + r1) = o;

    o = make_float4(sGat[id[0] * 3 + 2], sGat[id[1] * 3 + 2],
                    sGat[id[2] * 3 + 2], sGat[id[3] * 3 + 2]);
    *(float4*)(ob + 2 * HW + r0) = o;
    o = make_float4(sGat[id[4] * 3 + 2], sGat[id[5] * 3 + 2],
                    sGat[id[6] * 3 + 2], sGat[id[7] * 3 + 2]);
    *(float4*)(ob + 2 * HW + r1) = o;
}

extern "C" void kernel_launch(void* const* d_in, const int* in_sizes, int n_in,
                              void* d_out, int out_size) {
    const float* x  = (const float*)d_in[0];
    const float* W1 = (const float*)d_in[1];
    const float* b1 = (const float*)d_in[2];
    const float* W2 = (const float*)d_in[3];
    const float* b2 = (const float*)d_in[4];
    float* out = (float*)d_out;

    dim3 grid(GRIDX, B_DIM);   // 128 x 32 = 4096 CTAs, 8 px/thread
    dim3 block(TPB);
    color_quant_kernel<<<grid, block>>>(x, W1, b1, W2, b2, out);
}